// round 15
// baseline (speedup 1.0000x reference)
#include <cuda_runtime.h>
#include <cuda_bf16.h>
#include <math.h>
#include <stdint.h>

// Problem constants
#define BB   8
#define LL   3072
#define SS   3072
#define DD   512
#define HH   8
#define INDN 96
#define BLD  (BB*LL*DD)   // 12582912
#define PI_F 3.14159265358979323846f

typedef unsigned long long ull;

// ---------------------------------------------------------------------------
// Scratch (device globals; allocation-free per harness rules)
// ---------------------------------------------------------------------------
__device__ float g_K0   [(size_t)BB*SS*DD];
__device__ float g_V0   [(size_t)BB*SS*DD];
__device__ float g_Q0   [(size_t)INDN*DD];
__device__ float g_kom0 [(size_t)BB*SS*16];
__device__ float g_kth0 [(size_t)BB*SS*16];
__device__ float g_qom0 [(size_t)INDN*16];
__device__ float g_qth0 [(size_t)INDN*16];
__device__ float g_scores[(size_t)BB*HH*INDN*SS];
__device__ float g_attn0[(size_t)BB*INDN*DD];
__device__ float g_indB [(size_t)BB*INDN*DD];
__device__ float g_indC [(size_t)BB*INDN*DD];
__device__ float g_Q1   [(size_t)BB*LL*DD];
__device__ float g_K1   [(size_t)BB*INDN*DD];
__device__ float g_V1   [(size_t)BB*INDN*DD];
__device__ float g_qom1 [(size_t)BB*LL*16];
__device__ float g_qth1 [(size_t)BB*LL*16];
__device__ float g_kom1 [(size_t)BB*INDN*16];
__device__ float g_kth1 [(size_t)BB*INDN*16];
__device__ float g_pen[2];
__device__ float g_statM[(size_t)BB*HH*INDN];
__device__ float g_statI[(size_t)BB*HH*INDN];
// bf16 split buffers
__device__ __nv_bfloat16 g_ahi [(size_t)BB*SS*DD];
__device__ __nv_bfloat16 g_alo [(size_t)BB*SS*DD];
__device__ __nv_bfloat16 g_wThi[(size_t)DD*DD];
__device__ __nv_bfloat16 g_wTlo[(size_t)DD*DD];
__device__ __nv_bfloat16 g_qrh [(size_t)BB*LL*HH*128];
__device__ __nv_bfloat16 g_qrl [(size_t)BB*LL*HH*128];
__device__ __nv_bfloat16 g_krh [(size_t)BB*SS*HH*128];
__device__ __nv_bfloat16 g_krl [(size_t)BB*SS*HH*128];

// ---------------------------------------------------------------------------
// Packed f32x2 helpers
// ---------------------------------------------------------------------------
__device__ __forceinline__ ull pk2(float x, float y) {
    ull r;
    asm("mov.b64 %0, {%1, %2};" : "=l"(r) : "f"(x), "f"(y));
    return r;
}
__device__ __forceinline__ void fma2(ull& d, ull a, ull b) {
    asm("fma.rn.f32x2 %0, %1, %2, %0;" : "+l"(d) : "l"(a), "l"(b));
}
__device__ __forceinline__ float2 upk2(ull v) {
    float2 r;
    asm("mov.b64 {%0, %1}, %2;" : "=f"(r.x), "=f"(r.y) : "l"(v));
    return r;
}

// ---------------------------------------------------------------------------
// cp.async helpers (sm_80 baseline PTX)
// ---------------------------------------------------------------------------
__device__ __forceinline__ void cpa16(uint32_t dst, const void* src) {
    asm volatile("cp.async.cg.shared.global [%0], [%1], 16;"
                 :: "r"(dst), "l"(src) : "memory");
}
__device__ __forceinline__ void cpa16z(uint32_t dst, const void* src, bool v) {
    int sz = v ? 16 : 0;
    asm volatile("cp.async.cg.shared.global [%0], [%1], 16, %2;"
                 :: "r"(dst), "l"(src), "r"(sz) : "memory");
}
#define CPA_COMMIT asm volatile("cp.async.commit_group;" ::: "memory")
#define CPA_WAIT1  asm volatile("cp.async.wait_group 1;" ::: "memory")
#define CPA_WAIT0  asm volatile("cp.async.wait_group 0;" ::: "memory")

__device__ __forceinline__ uint32_t smem_u32(const void* p) {
    uint32_t a;
    asm("{ .reg .u64 t; cvta.to.shared.u64 t, %1; cvt.u32.u64 %0, t; }" : "=r"(a) : "l"(p));
    return a;
}

// ---------------------------------------------------------------------------
// bf16 mma helper (baseline PTX, sm_80+)
// ---------------------------------------------------------------------------
__device__ __forceinline__ void mma_bf16(float* c, const uint32_t* a, const uint32_t* b) {
    asm volatile(
        "mma.sync.aligned.m16n8k16.row.col.f32.bf16.bf16.f32 "
        "{%0,%1,%2,%3}, {%4,%5,%6,%7}, {%8,%9}, {%0,%1,%2,%3};"
        : "+f"(c[0]), "+f"(c[1]), "+f"(c[2]), "+f"(c[3])
        : "r"(a[0]), "r"(a[1]), "r"(a[2]), "r"(a[3]), "r"(b[0]), "r"(b[1]));
}

#define MMA_STAGE 40960
extern __shared__ char dynsm[];

// ---------------------------------------------------------------------------
// mma_nn_bf16: C[N,512] = (Ahi+Alo)[N,512] @ (WThi+WTlo)^T + bias
// __launch_bounds__(256,2): force 2 CTAs/SM to fill tensor-pipe bubbles.
// ---------------------------------------------------------------------------
__global__ __launch_bounds__(256, 2) void mma_nn_bf16(
    const __nv_bfloat16* __restrict__ Ahi, const __nv_bfloat16* __restrict__ Alo,
    const __nv_bfloat16* __restrict__ Bhi, const __nv_bfloat16* __restrict__ Blo,
    const float* __restrict__ bias, float* __restrict__ C, int N)
{
    uint32_t sb = smem_u32(dynsm);
    int tid = threadIdx.x;
    int rowBase = blockIdx.y * 128, colBase = blockIdx.x * 128;
    int wid = tid >> 5, lane = tid & 31;
    int mBase = (wid >> 2) * 64, nBase = (wid & 3) * 32;

    float c[4][4][4];
#pragma unroll
    for (int ma = 0; ma < 4; ma++)
#pragma unroll
        for (int na = 0; na < 4; na++)
#pragma unroll
            for (int i = 0; i < 4; i++) c[ma][na][i] = 0.f;

    auto issue = [&](int ck, int p) {
        uint32_t base = sb + p * MMA_STAGE;
        int k0 = ck * 32;
#pragma unroll
        for (int j = 0; j < 2; j++) {
            int i = tid + j * 256;
            int row = i >> 2, seg = i & 3;
            uint32_t off = (uint32_t)(row * 20 + seg * 4) * 4;
            size_t ga = (size_t)(rowBase + row) * 512 + k0 + seg * 8;
            cpa16(base + off,         Ahi + ga);
            cpa16(base + 10240 + off, Alo + ga);
            size_t gb = (size_t)(colBase + row) * 512 + k0 + seg * 8;
            cpa16(base + 20480 + off, Bhi + gb);
            cpa16(base + 30720 + off, Blo + gb);
        }
        CPA_COMMIT;
    };

    issue(0, 0);
    for (int ck = 0; ck < 16; ck++) {
        int p = ck & 1;
        if (ck < 15) { issue(ck + 1, p ^ 1); CPA_WAIT1; } else { CPA_WAIT0; }
        __syncthreads();
        const uint32_t* AsH = (const uint32_t*)(dynsm + p * MMA_STAGE);
        const uint32_t* AsL = AsH + 2560;
        const uint32_t* BsH = AsH + 5120;
        const uint32_t* BsL = AsH + 7680;
#pragma unroll
        for (int kk = 0; kk < 16; kk += 8) {
            int kq = kk + (lane & 3);
            uint32_t bh[4][2], bl[4][2];
#pragma unroll
            for (int na = 0; na < 4; na++) {
                int n = nBase + na * 8 + (lane >> 2);
                bh[na][0] = BsH[n * 20 + kq];     bh[na][1] = BsH[n * 20 + kq + 4];
                bl[na][0] = BsL[n * 20 + kq];     bl[na][1] = BsL[n * 20 + kq + 4];
            }
#pragma unroll
            for (int ma = 0; ma < 4; ma++) {
                int r = mBase + ma * 16 + (lane >> 2);
                uint32_t ah[4], al[4];
                ah[0] = AsH[r * 20 + kq];       ah[1] = AsH[(r + 8) * 20 + kq];
                ah[2] = AsH[r * 20 + kq + 4];   ah[3] = AsH[(r + 8) * 20 + kq + 4];
                al[0] = AsL[r * 20 + kq];       al[1] = AsL[(r + 8) * 20 + kq];
                al[2] = AsL[r * 20 + kq + 4];   al[3] = AsL[(r + 8) * 20 + kq + 4];
#pragma unroll
                for (int na = 0; na < 4; na++) mma_bf16(c[ma][na], ah, bh[na]);
#pragma unroll
                for (int na = 0; na < 4; na++) mma_bf16(c[ma][na], ah, bl[na]);
#pragma unroll
                for (int na = 0; na < 4; na++) mma_bf16(c[ma][na], al, bh[na]);
            }
        }
        __syncthreads();
    }

#pragma unroll
    for (int ma = 0; ma < 4; ma++) {
        int row0 = rowBase + mBase + ma * 16 + (lane >> 2);
        int row1 = row0 + 8;
#pragma unroll
        for (int na = 0; na < 4; na++) {
            int col = colBase + nBase + na * 8 + (lane & 3) * 2;
            float b0 = bias[col], b1 = bias[col + 1];
            if (row0 < N) {
                float2 o = make_float2(c[ma][na][0] + b0, c[ma][na][1] + b1);
                *(float2*)(C + (size_t)row0 * 512 + col) = o;
            }
            if (row1 < N) {
                float2 o = make_float2(c[ma][na][2] + b0, c[ma][na][3] + b1);
                *(float2*)(C + (size_t)row1 * 512 + col) = o;
            }
        }
    }
}

// ---------------------------------------------------------------------------
// mma_nt_bf16<MAS>: scores[bh,l,s] = (1/16) Qr.Kr per (b,h), K=128.
// ---------------------------------------------------------------------------
template<int MAS>
__global__ __launch_bounds__(256, 2) void mma_nt_bf16(
    const __nv_bfloat16* __restrict__ Qh, const __nv_bfloat16* __restrict__ Ql,
    size_t qBstride,
    const __nv_bfloat16* __restrict__ Kh, const __nv_bfloat16* __restrict__ Kl,
    float* __restrict__ scores, int Lq, int S)
{
    uint32_t sb = smem_u32(dynsm);
    int tid = threadIdx.x;
    int bh = blockIdx.z, b = bh >> 3, h = bh & 7;
    size_t aOff = (size_t)b * qBstride + (size_t)h * 128;
    size_t bOff = ((size_t)b * S * HH + h) * 128;
    float* C = scores + (size_t)bh * Lq * S;
    int lBase = blockIdx.y * 128, sBase = blockIdx.x * 128;
    int wid = tid >> 5, lane = tid & 31;
    int mBase = (wid >> 2) * (MAS * 16), nBase = (wid & 3) * 32;

    float c[MAS][4][4];
#pragma unroll
    for (int ma = 0; ma < MAS; ma++)
#pragma unroll
        for (int na = 0; na < 4; na++)
#pragma unroll
            for (int i = 0; i < 4; i++) c[ma][na][i] = 0.f;

    auto issue = [&](int ck, int p) {
        uint32_t base = sb + p * MMA_STAGE;
        int k0 = ck * 32;
#pragma unroll
        for (int j = 0; j < 2; j++) {
            int i = tid + j * 256;
            int row = i >> 2, seg = i & 3;
            uint32_t off = (uint32_t)(row * 20 + seg * 4) * 4;
            int gl = lBase + row;
            bool va = gl < Lq;
            size_t ga = aOff + (size_t)(va ? gl : 0) * 1024 + k0 + seg * 8;
            cpa16z(base + off,         Qh + ga, va);
            cpa16z(base + 10240 + off, Ql + ga, va);
            int gs = sBase + row;
            bool vb = gs < S;
            size_t gb = bOff + (size_t)(vb ? gs : 0) * 1024 + k0 + seg * 8;
            cpa16z(base + 20480 + off, Kh + gb, vb);
            cpa16z(base + 30720 + off, Kl + gb, vb);
        }
        CPA_COMMIT;
    };

    issue(0, 0);
    for (int ck = 0; ck < 4; ck++) {
        int p = ck & 1;
        if (ck < 3) { issue(ck + 1, p ^ 1); CPA_WAIT1; } else { CPA_WAIT0; }
        __syncthreads();
        const uint32_t* AsH = (const uint32_t*)(dynsm + p * MMA_STAGE);
        const uint32_t* AsL = AsH + 2560;
        const uint32_t* BsH = AsH + 5120;
        const uint32_t* BsL = AsH + 7680;
#pragma unroll
        for (int kk = 0; kk < 16; kk += 8) {
            int kq = kk + (lane & 3);
            uint32_t bhf[4][2], blf[4][2];
#pragma unroll
            for (int na = 0; na < 4; na++) {
                int n = nBase + na * 8 + (lane >> 2);
                bhf[na][0] = BsH[n * 20 + kq];  bhf[na][1] = BsH[n * 20 + kq + 4];
                blf[na][0] = BsL[n * 20 + kq];  blf[na][1] = BsL[n * 20 + kq + 4];
            }
#pragma unroll
            for (int ma = 0; ma < MAS; ma++) {
                int r = mBase + ma * 16 + (lane >> 2);
                uint32_t ah[4], al[4];
                ah[0] = AsH[r * 20 + kq];       ah[1] = AsH[(r + 8) * 20 + kq];
                ah[2] = AsH[r * 20 + kq + 4];   ah[3] = AsH[(r + 8) * 20 + kq + 4];
                al[0] = AsL[r * 20 + kq];       al[1] = AsL[(r + 8) * 20 + kq];
                al[2] = AsL[r * 20 + kq + 4];   al[3] = AsL[(r + 8) * 20 + kq + 4];
#pragma unroll
                for (int na = 0; na < 4; na++) mma_bf16(c[ma][na], ah, bhf[na]);
#pragma unroll
                for (int na = 0; na < 4; na++) mma_bf16(c[ma][na], ah, blf[na]);
#pragma unroll
                for (int na = 0; na < 4; na++) mma_bf16(c[ma][na], al, bhf[na]);
            }
        }
        __syncthreads();
    }

#pragma unroll
    for (int ma = 0; ma < MAS; ma++) {
        int l0 = lBase + mBase + ma * 16 + (lane >> 2);
        int l1 = l0 + 8;
#pragma unroll
        for (int na = 0; na < 4; na++) {
            int s = sBase + nBase + na * 8 + (lane & 3) * 2;
            if (s + 1 < S) {
                if (l0 < Lq) {
                    float2 o = make_float2(c[ma][na][0] * 0.0625f, c[ma][na][1] * 0.0625f);
                    *(float2*)(C + (size_t)l0 * S + s) = o;
                }
                if (l1 < Lq) {
                    float2 o = make_float2(c[ma][na][2] * 0.0625f, c[ma][na][3] * 0.0625f);
                    *(float2*)(C + (size_t)l1 * S + s) = o;
                }
            } else if (s < S) {
                if (l0 < Lq) C[(size_t)l0 * S + s] = c[ma][na][0] * 0.0625f;
                if (l1 < Lq) C[(size_t)l1 * S + s] = c[ma][na][2] * 0.0625f;
            }
        }
    }
}

// ---------------------------------------------------------------------------
// attn1_fused: layer-1 scores (mma, 3-term) + softmax + AV in one block.
// Output written directly as bf16 hi/lo (feeds the final Wo GEMM).
// ---------------------------------------------------------------------------
#define AT_QH 0
#define AT_QL 34816
#define AT_KH 69632
#define AT_KL 95744
#define AT_V  121856
#define AT_PS 146432
#define AT_SMEM 197632

__global__ __launch_bounds__(256) void attn1_fused(
    const __nv_bfloat16* __restrict__ Qh, const __nv_bfloat16* __restrict__ Ql,
    const __nv_bfloat16* __restrict__ Kh, const __nv_bfloat16* __restrict__ Kl,
    const float* __restrict__ V,
    __nv_bfloat16* __restrict__ Oh, __nv_bfloat16* __restrict__ Ol)
{
    uint32_t sb = smem_u32(dynsm);
    int tid = threadIdx.x, wid = tid >> 5, lane = tid & 31;
    int lBase = blockIdx.x * 128, h = blockIdx.y, b = blockIdx.z;

#pragma unroll
    for (int i = 0; i < 8; i++) {
        int seg = tid + i * 256;
        int row = seg >> 4, sg = seg & 15;
        size_t g = ((size_t)(b * LL + lBase + row) * HH + h) * 128 + sg * 8;
        uint32_t so = (uint32_t)(row * 272 + sg * 16);
        cpa16(sb + AT_QH + so, Qh + g);
        cpa16(sb + AT_QL + so, Ql + g);
    }
#pragma unroll
    for (int i = 0; i < 6; i++) {
        int seg = tid + i * 256;
        int row = seg >> 4, sg = seg & 15;
        size_t g = ((size_t)(b * INDN + row) * HH + h) * 128 + sg * 8;
        uint32_t so = (uint32_t)(row * 272 + sg * 16);
        cpa16(sb + AT_KH + so, Kh + g);
        cpa16(sb + AT_KL + so, Kl + g);
        size_t gv = (size_t)(b * INDN + row) * 512 + h * 64 + sg * 4;
        cpa16(sb + AT_V + (uint32_t)(row * 256 + sg * 16), V + gv);
    }
    CPA_COMMIT; CPA_WAIT0;
    __syncthreads();

    int mBase = wid * 16;
    float c[12][4];
#pragma unroll
    for (int nt = 0; nt < 12; nt++)
#pragma unroll
        for (int i = 0; i < 4; i++) c[nt][i] = 0.f;

    int r0 = mBase + (lane >> 2);
#pragma unroll
    for (int kk = 0; kk < 8; kk++) {
        int kq4 = (kk * 8 + (lane & 3)) * 4;
        uint32_t ah[4], al[4];
        ah[0] = *(const uint32_t*)(dynsm + AT_QH + r0 * 272 + kq4);
        ah[1] = *(const uint32_t*)(dynsm + AT_QH + (r0 + 8) * 272 + kq4);
        ah[2] = *(const uint32_t*)(dynsm + AT_QH + r0 * 272 + kq4 + 16);
        ah[3] = *(const uint32_t*)(dynsm + AT_QH + (r0 + 8) * 272 + kq4 + 16);
        al[0] = *(const uint32_t*)(dynsm + AT_QL + r0 * 272 + kq4);
        al[1] = *(const uint32_t*)(dynsm + AT_QL + (r0 + 8) * 272 + kq4);
        al[2] = *(const uint32_t*)(dynsm + AT_QL + r0 * 272 + kq4 + 16);
        al[3] = *(const uint32_t*)(dynsm + AT_QL + (r0 + 8) * 272 + kq4 + 16);
        uint32_t bhf[12][2], blf[12][2];
#pragma unroll
        for (int nt = 0; nt < 12; nt++) {
            int n = nt * 8 + (lane >> 2);
            bhf[nt][0] = *(const uint32_t*)(dynsm + AT_KH + n * 272 + kq4);
            bhf[nt][1] = *(const uint32_t*)(dynsm + AT_KH + n * 272 + kq4 + 16);
            blf[nt][0] = *(const uint32_t*)(dynsm + AT_KL + n * 272 + kq4);
            blf[nt][1] = *(const uint32_t*)(dynsm + AT_KL + n * 272 + kq4 + 16);
        }
#pragma unroll
        for (int nt = 0; nt < 12; nt++) mma_bf16(c[nt], ah, bhf[nt]);
#pragma unroll
        for (int nt = 0; nt < 12; nt++) mma_bf16(c[nt], ah, blf[nt]);
#pragma unroll
        for (int nt = 0; nt < 12; nt++) mma_bf16(c[nt], al, bhf[nt]);
    }

#pragma unroll
    for (int nt = 0; nt < 12; nt++) {
        int s = nt * 8 + (lane & 3) * 2;
        *(float2*)(dynsm + AT_PS + r0 * 400 + s * 4) =
            make_float2(c[nt][0] * 0.0625f, c[nt][1] * 0.0625f);
        *(float2*)(dynsm + AT_PS + (r0 + 8) * 400 + s * 4) =
            make_float2(c[nt][2] * 0.0625f, c[nt][3] * 0.0625f);
    }
    __syncthreads();

    const float* Vsm = (const float*)(dynsm + AT_V);
#pragma unroll 4
    for (int rr = 0; rr < 16; rr++) {
        int row = mBase + rr;
        const float* PsRow = (const float*)(dynsm + AT_PS + row * 400);
        float pr[3];
        pr[0] = PsRow[lane]; pr[1] = PsRow[lane + 32]; pr[2] = PsRow[lane + 64];
        float m = fmaxf(pr[0], fmaxf(pr[1], pr[2]));
#pragma unroll
        for (int off = 16; off > 0; off >>= 1)
            m = fmaxf(m, __shfl_xor_sync(0xffffffffu, m, off));
        pr[0] = __expf(pr[0] - m); pr[1] = __expf(pr[1] - m); pr[2] = __expf(pr[2] - m);
        float ssum = pr[0] + pr[1] + pr[2];
#pragma unroll
        for (int off = 16; off > 0; off >>= 1)
            ssum += __shfl_xor_sync(0xffffffffu, ssum, off);
        float inv = 1.f / ssum;
        float a0 = 0.f, a1 = 0.f;
#pragma unroll
        for (int j = 0; j < 3; j++)
#pragma unroll
            for (int sl = 0; sl < 32; sl++) {
                float ps = __shfl_sync(0xffffffffu, pr[j], sl);
                int s = j * 32 + sl;
                a0 = fmaf(ps, Vsm[s * 64 + lane], a0);
                a1 = fmaf(ps, Vsm[s * 64 + lane + 32], a1);
            }
        float r0v = a0 * inv, r1v = a1 * inv;
        size_t ob = ((size_t)(b * LL + lBase + row)) * 512 + h * 64;
        __nv_bfloat16 h0 = __float2bfloat16(r0v);
        __nv_bfloat16 h1 = __float2bfloat16(r1v);
        Oh[ob + lane]      = h0;
        Oh[ob + lane + 32] = h1;
        Ol[ob + lane]      = __float2bfloat16(r0v - __bfloat162float(h0));
        Ol[ob + lane + 32] = __float2bfloat16(r1v - __bfloat162float(h1));
    }
}

// ---------------------------------------------------------------------------
// Split fp32 -> (hi, lo) bf16
// ---------------------------------------------------------------------------
__global__ __launch_bounds__(256) void split_f32(
    const float* __restrict__ x, __nv_bfloat16* __restrict__ hi,
    __nv_bfloat16* __restrict__ lo, int n4)
{
    for (int i = blockIdx.x * 256 + threadIdx.x; i < n4; i += gridDim.x * 256) {
        float4 v = ((const float4*)x)[i];
        __nv_bfloat16 h0 = __float2bfloat16(v.x);
        __nv_bfloat16 h1 = __float2bfloat16(v.y);
        __nv_bfloat16 h2 = __float2bfloat16(v.z);
        __nv_bfloat16 h3 = __float2bfloat16(v.w);
        __nv_bfloat162* hp = (__nv_bfloat162*)hi;
        __nv_bfloat162* lp = (__nv_bfloat162*)lo;
        hp[2*i]   = __nv_bfloat162(h0, h1);
        hp[2*i+1] = __nv_bfloat162(h2, h3);
        lp[2*i]   = __nv_bfloat162(__float2bfloat16(v.x - __bfloat162float(h0)),
                                   __float2bfloat16(v.y - __bfloat162float(h1)));
        lp[2*i+1] = __nv_bfloat162(__float2bfloat16(v.z - __bfloat162float(h2)),
                                   __float2bfloat16(v.w - __bfloat162float(h3)));
    }
}

// ---------------------------------------------------------------------------
// Split + transpose W[512,512] -> WT hi/lo
// ---------------------------------------------------------------------------
__global__ __launch_bounds__(256) void split_wT(
    const float* __restrict__ W, __nv_bfloat16* __restrict__ hiT,
    __nv_bfloat16* __restrict__ loT)
{
    __shared__ float t[32][33];
    int bn = blockIdx.x * 32;
    int bk = blockIdx.y * 32;
    int tx = threadIdx.x & 31, ty = threadIdx.x >> 5;
    for (int r = ty; r < 32; r += 8)
        t[r][tx] = W[(size_t)(bk + r) * 512 + bn + tx];
    __syncthreads();
    for (int r = ty; r < 32; r += 8) {
        float v = t[tx][r];
        __nv_bfloat16 h = __float2bfloat16(v);
        size_t o = (size_t)(bn + r) * 512 + bk + tx;
        hiT[o] = h;
        loT[o] = __float2bfloat16(v - __bfloat162float(h));
    }
}

// ---------------------------------------------------------------------------
// FFMA2 GEMM (NN) for small exact-fp32 GEMMs
// ---------------------------------------------------------------------------
__global__ __launch_bounds__(256, 2) void gemm_nn(
    const float* __restrict__ A, const float* __restrict__ W,
    const float* __restrict__ bias, float* __restrict__ C, int N, int P)
{
    __shared__ float As[16][132];
    __shared__ float Bs[16][132];
    int tid = threadIdx.x;
    int rowBase = blockIdx.y * 128;
    int colBase = blockIdx.x * 128;
    int ty = tid >> 4, tx = tid & 15;

    ull acc[4][8];
#pragma unroll
    for (int p = 0; p < 4; p++)
#pragma unroll
        for (int j = 0; j < 8; j++) acc[p][j] = 0ull;

    int aRow = tid >> 2;
    int aK   = (tid & 3) * 4;
    int bK   = tid >> 4;
    int bCol = (tid & 15) * 4;
    bool v0 = (rowBase + aRow) < N;
    bool v1 = (rowBase + aRow + 64) < N;
    const float* Ap0 = A + (size_t)(rowBase + aRow) * 512 + aK;
    const float* Ap1 = Ap0 + (size_t)64 * 512;
    const float* Wp  = W + (size_t)bK * P + colBase + bCol;

    for (int k0 = 0; k0 < 512; k0 += 16) {
        float4 a0 = v0 ? *(const float4*)(Ap0 + k0) : make_float4(0.f,0.f,0.f,0.f);
        float4 a1 = v1 ? *(const float4*)(Ap1 + k0) : make_float4(0.f,0.f,0.f,0.f);
        As[aK+0][aRow] = a0.x; As[aK+1][aRow] = a0.y;
        As[aK+2][aRow] = a0.z; As[aK+3][aRow] = a0.w;
        As[aK+0][aRow+64] = a1.x; As[aK+1][aRow+64] = a1.y;
        As[aK+2][aRow+64] = a1.z; As[aK+3][aRow+64] = a1.w;
        float4 b0 = *(const float4*)(Wp + (size_t)k0 * P);
        float4 b1 = *(const float4*)(Wp + (size_t)k0 * P + 64);
        *(float4*)&Bs[bK][bCol]      = b0;
        *(float4*)&Bs[bK][bCol + 64] = b1;
        __syncthreads();
#pragma unroll
        for (int k = 0; k < 16; k++) {
            float4 av0 = *(const float4*)&As[k][ty*4];
            float4 av1 = *(const float4*)&As[k][64 + ty*4];
            float4 bv0 = *(const float4*)&Bs[k][tx*4];
            float4 bv1 = *(const float4*)&Bs[k][64 + tx*4];
            ull ap[4];
            ap[0] = pk2(av0.x, av0.y); ap[1] = pk2(av0.z, av0.w);
            ap[2] = pk2(av1.x, av1.y); ap[3] = pk2(av1.z, av1.w);
            ull bd[8];
            bd[0] = pk2(bv0.x, bv0.x); bd[1] = pk2(bv0.y, bv0.y);
            bd[2] = pk2(bv0.z, bv0.z); bd[3] = pk2(bv0.w, bv0.w);
            bd[4] = pk2(bv1.x, bv1.x); bd[5] = pk2(bv1.y, bv1.y);
            bd[6] = pk2(bv1.z, bv1.z); bd[7] = pk2(bv1.w, bv1.w);
#pragma unroll
            for (int p = 0; p < 4; p++)
#pragma unroll
                for (int j = 0; j < 8; j++)
                    fma2(acc[p][j], ap[p], bd[j]);
        }
        __syncthreads();
    }

#pragma unroll
    for (int p = 0; p < 4; p++) {
        int row = rowBase + ((p < 2) ? (ty*4 + p*2) : (64 + ty*4 + (p-2)*2));
#pragma unroll
        for (int j = 0; j < 8; j++) {
            int col = colBase + ((j < 4) ? (tx*4 + j) : (64 + tx*4 + (j-4)));
            float2 r = upk2(acc[p][j]);
            float bb = bias[col];
            if (row < N)     C[(size_t)row * P + col]     = r.x + bb;
            if (row + 1 < N) C[(size_t)(row+1) * P + col] = r.y + bb;
        }
    }
}

// ---------------------------------------------------------------------------
// Fused omega/theta heads
// ---------------------------------------------------------------------------
__global__ __launch_bounds__(256) void gemm_omth(
    const float* __restrict__ A,
    const float* __restrict__ Wom, const float* __restrict__ bom,
    const float* __restrict__ Wth, const float* __restrict__ bth,
    float* __restrict__ Com, float* __restrict__ Cth, int N)
{
    __shared__ float As[16][68];
    __shared__ float Ws[16][34];
    int tid = threadIdx.x;
    int rowBase = blockIdx.x * 64;
    int ty = tid >> 4, tx = tid & 15;
    float acc[4][2] = {{0.f,0.f},{0.f,0.f},{0.f,0.f},{0.f,0.f}};

    int aRow = tid >> 2;
    int aK   = (tid & 3) * 4;
    int wK   = tid >> 4;
    int wC   = tid & 15;
    bool av = (rowBase + aRow) < N;
    const float* Ap = A + (size_t)(rowBase + aRow) * 512 + aK;

    for (int k0 = 0; k0 < 512; k0 += 16) {
        float4 a = av ? *(const float4*)(Ap + k0) : make_float4(0.f,0.f,0.f,0.f);
        As[aK+0][aRow] = a.x; As[aK+1][aRow] = a.y;
        As[aK+2][aRow] = a.z; As[aK+3][aRow] = a.w;
        Ws[wK][wC]      = Wom[(size_t)(k0 + wK) * 16 + wC];
        Ws[wK][16 + wC] = Wth[(size_t)(k0 + wK) * 16 + wC];
        __syncthreads();
#pragma unroll
        for (int k = 0; k < 16; k++) {
            float4 avv = *(const float4*)&As[k][ty*4];
            float w0 = Ws[k][tx], w1 = Ws[k][16 + tx];
            acc[0][0] = fmaf(avv.x, w0, acc[0][0]); acc[0][1] = fmaf(avv.x, w1, acc[0][1]);
            acc[1][0] = fmaf(avv.y, w0, acc[1][0]); acc[1][1] = fmaf(avv.y, w1, acc[1][1]);
            acc[2][0] = fmaf(avv.z, w0, acc[2][0]); acc[2][1] = fmaf(avv.z, w1, acc[2][1]);
            acc[3][0] = fmaf(avv.w, w0, acc[3][0]); acc[3][1] = fmaf(avv.w, w1, acc[3][1]);
        }
        __syncthreads();
    }
#pragma unroll
    for (int i = 0; i < 4; i++) {
        int row = rowBase + ty*4 + i;
        if (row >= N) continue;
        Com[(size_t)row * 16 + tx] = fmaxf(acc[i][0] + bom[tx], 0.f);
        Cth[(size_t)row * 16 + tx] = tanhf(acc[i][1] + bth[tx]) * PI_F;
    }
}

// ---------------------------------------------------------------------------
// Rotation builders -> bf16 hi/lo
// ---------------------------------------------------------------------------
__device__ __forceinline__ void wr_split(__nv_bfloat16* hi, __nv_bfloat16* lo,
                                         int idx, float v) {
    __nv_bfloat16 h = __float2bfloat16(v);
    hi[idx] = h;
    lo[idx] = __float2bfloat16(v - __bfloat162float(h));
}

__global__ void build_qr(const float* __restrict__ Q, const float* __restrict__ om,
                         const float* __restrict__ th,
                         __nv_bfloat16* __restrict__ Qh, __nv_bfloat16* __restrict__ Ql,
                         int seq, float invSeq)
{
    int row = blockIdx.x;
    int tid = threadIdx.x;
    int h = tid >> 5, m = (tid >> 4) & 1, i = tid & 15;
    float pos = (float)(row % seq) * invSeq;
    int oi = row * 16 + h * 2 + m;
    float ang = fmaf(om[oi], pos, th[oi]);
    float sn, cs; sincosf(ang, &sn, &cs);
    const float* q = Q + (size_t)row * 512 + h * 64;
    float q0 = q[i], q1 = q[16+i], q2 = q[32+i], q3 = q[48+i];
    int o = ((row * HH + h) * 128) + m * 64;
    wr_split(Qh, Ql, o + i,      q0*cs - q1*sn);
    wr_split(Qh, Ql, o + 16 + i, q1*cs + q0*sn);
    wr_split(Qh, Ql, o + 32 + i, q2*cs + q3*sn);
    wr_split(Qh, Ql, o + 48 + i, q3*cs - q2*sn);
}

__global__ void build_kr(const float* __restrict__ K, const float* __restrict__ om,
                         const float* __restrict__ th,
                         __nv_bfloat16* __restrict__ Kh, __nv_bfloat16* __restrict__ Kl,
                         int seq, float invSeq)
{
    int row = blockIdx.x;
    int tid = threadIdx.x;
    int h = tid >> 5, m = (tid >> 4) & 1, i = tid & 15;
    float pos = (float)(row % seq) * invSeq;
    int oi = row * 16 + h * 2 + m;
    float ang = fmaf(om[oi], pos, th[oi]);
    float sn, cs; sincosf(ang, &sn, &cs);
    const float* k = K + (size_t)row * 512 + h * 64;
    float k0 = k[i], k1 = k[16+i], k2 = k[32+i], k3 = k[48+i];
    int o = ((row * HH + h) * 128) + m * 64;
    wr_split(Kh, Kl, o + i,      k0*cs - k2*sn);
    wr_split(Kh, Kl, o + 16 + i, k1*cs - k3*sn);
    wr_split(Kh, Kl, o + 32 + i, k2*cs + k0*sn);
    wr_split(Kh, Kl, o + 48 + i, k3*cs + k1*sn);
}

// ---------------------------------------------------------------------------
// row_stats: per-row max and 1/sum(exp) for layer-0 softmax
// ---------------------------------------------------------------------------
__global__ __launch_bounds__(256) void row_stats(
    const float* __restrict__ scores, float* __restrict__ M, float* __restrict__ I)
{
    int row = blockIdx.x * 8 + (threadIdx.x >> 5);
    int lane = threadIdx.x & 31;
    const float* r = scores + (size_t)row * SS;
    float m = -3.4e38f;
    for (int i = lane; i < SS; i += 32) m = fmaxf(m, r[i]);
#pragma unroll
    for (int o = 16; o; o >>= 1) m = fmaxf(m, __shfl_xor_sync(0xffffffffu, m, o));
    float s = 0.f;
    for (int i = lane; i < SS; i += 32) s += __expf(r[i] - m);
#pragma unroll
    for (int o = 16; o; o >>= 1) s += __shfl_xor_sync(0xffffffffu, s, o);
    if (lane == 0) { M[row] = m; I[row] = 1.f / s; }
}

// ---------------------------------------------------------------------------
// av48: tiled softmax-weighted AV for layer 0
// ---------------------------------------------------------------------------
__global__ __launch_bounds__(256) void av48(
    const float* __restrict__ scores, const float* __restrict__ V,
    const float* __restrict__ M, const float* __restrict__ I,
    float* __restrict__ out)
{
    __shared__ float Vs[64][64];
    __shared__ float Ps[48][65];
    __shared__ float Ms[48], Is[48];
    int h = blockIdx.y, b = blockIdx.z;
    int l0 = blockIdx.x * 48;
    int bh = b * HH + h;
    int tid = threadIdx.x;
    int eg = tid & 15;
    int rg = tid >> 4;
    if (tid < 48) {
        Ms[tid] = M[bh * INDN + l0 + tid];
        Is[tid] = I[bh * INDN + l0 + tid];
    }
    const float* S0 = scores + ((size_t)bh * INDN + l0) * SS;
    const float* Vb = V + ((size_t)b * SS) * 512 + h * 64;
    __syncthreads();
    ull acc[3][2] = {{0ull,0ull},{0ull,0ull},{0ull,0ull}};
    for (int s0 = 0; s0 < SS; s0 += 64) {
#pragma unroll
        for (int i = 0; i < 4; i++) {
            int s = (tid >> 4) + i * 16;
            *(float4*)&Vs[s][eg * 4] = *(const float4*)&Vb[(size_t)(s0 + s) * 512 + eg * 4];
        }
#pragma unroll
        for (int i = 0; i < 3; i++) {
            int idx = tid + i * 256;
            int r = idx >> 4, sseg = idx & 15;
            float4 v = *(const float4*)&S0[(size_t)r * SS + s0 + sseg * 4];
            float m = Ms[r];
            Ps[r][sseg*4+0] = __expf(v.x - m);
            Ps[r][sseg*4+1] = __expf(v.y - m);
            Ps[r][sseg*4+2] = __expf(v.z - m);
            Ps[r][sseg*4+3] = __expf(v.w - m);
        }
        __syncthreads();
#pragma unroll 4
        for (int s = 0; s < 64; s++) {
            float4 v = *(const float4*)&Vs[s][eg * 4];
            ull vA = pk2(v.x, v.y), vB = pk2(v.z, v.w);
#pragma unroll
            for (int j = 0; j < 3; j++) {
                float p = Ps[rg * 3 + j][s];
                ull pp = pk2(p, p);
                fma2(acc[j][0], pp, vA);
                fma2(acc[j][1], pp, vB);
            }
        }
        __syncthreads();
    }
#pragma unroll
    for (int j = 0; j < 3; j++) {
        int l = l0 + rg * 3 + j;
        float inv = Is[rg * 3 + j];
        float2 a = upk2(acc[j][0]), bq = upk2(acc[j][1]);
        float* o = out + ((size_t)b * INDN + l) * 512 + h * 64 + eg * 4;
        *(float4*)o = make_float4(a.x * inv, a.y * inv, bq.x * inv, bq.y * inv);
    }
}

// ---------------------------------------------------------------------------
// Trend norm
// ---------------------------------------------------------------------------
__global__ __launch_bounds__(256) void trend_norm(
    const float* __restrict__ x, const float* __restrict__ gm,
    const float* __restrict__ bt, float* __restrict__ y)
{
    __shared__ float seas[512];
    __shared__ float trend[512];
    __shared__ float red[256];
    int b = blockIdx.y, t = blockIdx.x, tid = threadIdx.x;
    const float* xb = x + (size_t)b * INDN * 512;
    float ls = 0.f, ls2 = 0.f;
    for (int d = tid; d < 512; d += 256) {
        float tr = 0.f;
#pragma unroll
        for (int j = -12; j <= 12; j++) {
            int tt = t + j;
            tt = tt < 0 ? 0 : (tt > INDN-1 ? INDN-1 : tt);
            tr += xb[(size_t)tt * 512 + d];
        }
        tr *= (1.0f / 25.0f);
        float sv = xb[(size_t)t * 512 + d] - tr;
        seas[d] = sv; trend[d] = tr;
        ls += sv; ls2 += sv * sv;
    }
    red[tid] = ls; __syncthreads();
    for (int off = 128; off > 0; off >>= 1) { if (tid < off) red[tid] += red[tid+off]; __syncthreads(); }
    float mu = red[0] * (1.f/512.f); __syncthreads();
    red[tid] = ls2; __syncthreads();
    for (int off = 128; off > 0; off >>= 1) { if (tid < off) red[tid] += red[tid+off]; __syncthreads(); }
    float var = red[0] * (1.f/512.f) - mu*mu;
    float rs = rsqrtf(var + 1e-5f);
    for (int d = tid; d < 512; d += 256)
        y[((size_t)b*INDN + t) * 512 + d] = (seas[d] - mu) * rs * gm[d] + bt[d] + trend[d];
}

// ---------------------------------------------------------------------------
// Penalties
// ---------------------------------------------------------------------------
__global__ void zero_pen() { g_pen[0] = 0.f; g_pen[1] = 0.f; }

__global__ __launch_bounds__(256) void penalty_kernel(
    const float* __restrict__ om, const float* __restrict__ th,
    int total, int seq, float scale)
{
    float omp = 0.f, thp = 0.f;
    for (int idx = blockIdx.x * 256 + threadIdx.x; idx < total; idx += gridDim.x * 256) {
        int n = idx >> 4;
        int sIn = n % seq;
        float t = th[idx]; thp += t * t;
        if (sIn < seq - 1) { float d = om[idx + 16] - om[idx]; omp += d * d; }
    }
#pragma unroll
    for (int o = 16; o > 0; o >>= 1) {
        omp += __shfl_down_sync(0xffffffffu, omp, o);
        thp += __shfl_down_sync(0xffffffffu, thp, o);
    }
    __shared__ float sho[8], sht[8];
    int wid = threadIdx.x >> 5, lid = threadIdx.x & 31;
    if (lid == 0) { sho[wid] = omp; sht[wid] = thp; }
    __syncthreads();
    if (threadIdx.x == 0) {
        float so = 0.f, st = 0.f;
        for (int w = 0; w < 8; w++) { so += sho[w]; st += sht[w]; }
        atomicAdd(&g_pen[0], so * scale);
        atomicAdd(&g_pen[1], st * scale);
    }
}

__global__ void finalize_kernel(float* out, int out_size)
{
    if (out_size >= BLD + 2) {
        out[BLD]     = g_pen[0];
        out[BLD + 1] = g_pen[1];
    }
}

// ---------------------------------------------------------------------------
// Host launcher (sequential)
// ---------------------------------------------------------------------------
#define SYMADDR(p, s) do { void* _t = nullptr; cudaGetSymbolAddress(&_t, s); (p) = decltype(p)(_t); } while (0)

extern "C" void kernel_launch(void* const* d_in, const int* in_sizes, int n_in,
                              void* d_out, int out_size)
{
    (void)in_sizes; (void)n_in;
    const float* queries = (const float*)d_in[0];
    const float* keys    = (const float*)d_in[1];
    const float* values  = (const float*)d_in[2];
    const float* Wq  = (const float*)d_in[3];
    const float* bq  = (const float*)d_in[4];
    const float* Wk  = (const float*)d_in[5];
    const float* bk  = (const float*)d_in[6];
    const float* Wv  = (const float*)d_in[7];
    const float* bv  = (const float*)d_in[8];
    const float* Wqo = (const float*)d_in[9];
    const float* bqo = (const float*)d_in[10];
    const float* Wko = (const float*)d_in[11];
    const float* bko = (const float*)d_in[12];
    const float* Wqt = (const float*)d_in[13];
    const float* bqt = (const float*)d_in[14];
    const float* Wkt = (const float*)d_in[15];
    const float* bkt = (const float*)d_in[16];
    const float* Wo  = (const float*)d_in[17];
    const float* bo  = (const float*)d_in[18];
    const float* Ibuf = (const float*)d_in[19];
    const float* ln_g = (const float*)d_in[20];
    const float* ln_b = (const float*)d_in[21];
    float* out = (float*)d_out;

    const int NBS = BB * SS;      // 24576
    const int NBI = BB * INDN;    // 768
    const int W2  = 512 * 512;
    const int W2S = 512 * 16;
    const int N4  = NBS * 512 / 4;
    const int MMA_DSM = 2 * MMA_STAGE;  // 81920

    float *pK0, *pV0, *pQ0, *pkom0, *pkth0, *pqom0, *pqth0, *pScores;
    float *pAttn0, *pIndB, *pIndC, *pQ1, *pK1, *pV1, *pqom1, *pqth1, *pkom1, *pkth1;
    float *pStatM, *pStatI;
    __nv_bfloat16 *pAhi, *pAlo, *pWThi, *pWTlo, *pQrh, *pQrl, *pKrh, *pKrl;
    SYMADDR(pK0, g_K0);     SYMADDR(pV0, g_V0);     SYMADDR(pQ0, g_Q0);
    SYMADDR(pkom0, g_kom0); SYMADDR(pkth0, g_kth0);
    SYMADDR(pqom0, g_qom0); SYMADDR(pqth0, g_qth0);
    SYMADDR(pScores, g_scores);
    SYMADDR(pAttn0, g_attn0); SYMADDR(pIndB, g_indB); SYMADDR(pIndC, g_indC);
    SYMADDR(pQ1, g_Q1);     SYMADDR(pK1, g_K1);     SYMADDR(pV1, g_V1);
    SYMADDR(pqom1, g_qom1); SYMADDR(pqth1, g_qth1);
    SYMADDR(pkom1, g_kom1); SYMADDR(pkth1, g_kth1);
    SYMADDR(pStatM, g_statM); SYMADDR(pStatI, g_statI);
    SYMADDR(pAhi, g_ahi);   SYMADDR(pAlo, g_alo);
    SYMADDR(pWThi, g_wThi); SYMADDR(pWTlo, g_wTlo);
    SYMADDR(pQrh, g_qrh);   SYMADDR(pQrl, g_qrl);
    SYMADDR(pKrh, g_krh);   SYMADDR(pKrl, g_krl);

    cudaFuncSetAttribute(mma_nn_bf16, cudaFuncAttributeMaxDynamicSharedMemorySize, MMA_DSM);
    cudaFuncSetAttribute(mma_nt_bf16<3>, cudaFuncAttributeMaxDynamicSharedMemorySize, MMA_DSM);
    cudaFuncSetAttribute(attn1_fused, cudaFuncAttributeMaxDynamicSharedMemorySize, AT_SMEM);

    dim3 gBig(4, NBS / 128);
    dim3 gWT(16, 16);

    // ------------------------ Layer 0 (inducings x keys/values) -------------
    split_f32<<<2048, 256>>>(keys, pAhi, pAlo, N4);
    split_wT<<<gWT, 256>>>(Wk, pWThi, pWTlo);
    mma_nn_bf16<<<gBig, 256, MMA_DSM>>>(pAhi, pAlo, pWThi, pWTlo, bk, pK0, NBS);

    split_f32<<<2048, 256>>>(values, pAhi, pAlo, N4);
    split_wT<<<gWT, 256>>>(Wv, pWThi, pWTlo);
    mma_nn_bf16<<<gBig, 256, MMA_DSM>>>(pAhi, pAlo, pWThi, pWTlo, bv, pV0, NBS);

    gemm_nn<<<dim3(4, 1), 256>>>(Ibuf, Wq, bq, pQ0, INDN, 512);

    gemm_omth<<<NBS/64, 256>>>(keys, Wko, bko, Wkt, bkt, pkom0, pkth0, NBS);
    gemm_omth<<<(INDN+63)/64, 256>>>(Ibuf, Wqo, bqo, Wqt, bqt, pqom0, pqth0, INDN);

    zero_pen<<<1, 1>>>();
    penalty_kernel<<<6, 256>>>(pqom0, pqth0, INDN*16, INDN, (float)BB);
    penalty_kernel<<<1024, 256>>>(pkom0, pkth0, NBS*16, SS, 1.f);

    build_qr<<<INDN, 256>>>(pQ0, pqom0, pqth0, pQrh, pQrl, INDN, 1.f/INDN);
    build_kr<<<NBS,  256>>>(pK0, pkom0, pkth0, pKrh, pKrl, SS,   1.f/SS);

    mma_nt_bf16<3><<<dim3(SS/128, 1, BB*HH), 256, MMA_DSM>>>(pQrh, pQrl, (size_t)0,
                                                             pKrh, pKrl, pScores, INDN, SS);
    row_stats<<<BB*HH*INDN/8, 256>>>(pScores, pStatM, pStatI);
    av48<<<dim3(2, HH, BB), 256>>>(pScores, pV0, pStatM, pStatI, pAttn0);

    gemm_nn<<<dim3(4, 6), 256>>>(pAttn0, Wo, bo, pIndB, NBI, 512);
    trend_norm<<<dim3(INDN, BB), 256>>>(pIndB, ln_g, ln_b, pIndC);

    // ------------------------ Layer 1 (queries x inducings) -----------------
    split_f32<<<2048, 256>>>(queries, pAhi, pAlo, N4);
    split_wT<<<gWT, 256>>>(Wq + W2, pWThi, pWTlo);
    mma_nn_bf16<<<gBig, 256, MMA_DSM>>>(pAhi, pAlo, pWThi, pWTlo, bq + 512, pQ1, NBS);

    gemm_nn<<<dim3(4, 6), 256>>>(pIndC, Wk + W2, bk + 512, pK1, NBI, 512);
    gemm_nn<<<dim3(4, 6), 256>>>(pIndC, Wv + W2, bv + 512, pV1, NBI, 512);

    gemm_omth<<<NBS/64, 256>>>(queries, Wqo + W2S, bqo + 16, Wqt + W2S, bqt + 16,
                               pqom1, pqth1, NBS);
    gemm_omth<<<NBI/64, 256>>>(pIndC, Wko + W2S, bko + 16, Wkt + W2S, bkt + 16,
                               pkom1, pkth1, NBI);

    penalty_kernel<<<1024, 256>>>(pqom1, pqth1, NBS*16, LL, 1.f);
    penalty_kernel<<<48, 256>>>(pkom1, pkth1, NBI*16, INDN, 1.f);

    build_qr<<<NBS, 256>>>(pQ1, pqom1, pqth1, pQrh, pQrl, LL,   1.f/LL);
    build_kr<<<NBI, 256>>>(pK1, pkom1, pkth1, pKrh, pKrl, INDN, 1.f/INDN);

    // fused attention writes bf16 hi/lo directly into the final-GEMM A buffers
    attn1_fused<<<dim3(LL/128, HH, BB), 256, AT_SMEM>>>(pQrh, pQrl, pKrh, pKrl,
                                                        pV1, pAhi, pAlo);

    split_wT<<<gWT, 256>>>(Wo + W2, pWThi, pWTlo);
    mma_nn_bf16<<<gBig, 256, MMA_DSM>>>(pAhi, pAlo, pWThi, pWTlo, bo + 512, out, NBS);

    finalize_kernel<<<1, 1>>>(out, out_size);
}

// round 17
// speedup vs baseline: 1.4803x; 1.4803x over previous
#include <cuda_runtime.h>
#include <cuda_bf16.h>
#include <math.h>
#include <stdint.h>

// Problem constants
#define BB   8
#define LL   3072
#define SS   3072
#define DD   512
#define HH   8
#define INDN 96
#define BLD  (BB*LL*DD)   // 12582912
#define PI_F 3.14159265358979323846f

typedef unsigned long long ull;

// ---------------------------------------------------------------------------
// Scratch (device globals; allocation-free per harness rules)
// ---------------------------------------------------------------------------
__device__ float g_K0   [(size_t)BB*SS*DD];
__device__ float g_V0   [(size_t)BB*SS*DD];
__device__ float g_Q0   [(size_t)INDN*DD];
__device__ float g_kom0 [(size_t)BB*SS*16];
__device__ float g_kth0 [(size_t)BB*SS*16];
__device__ float g_qom0 [(size_t)INDN*16];
__device__ float g_qth0 [(size_t)INDN*16];
__device__ float g_scores[(size_t)BB*HH*INDN*SS];
__device__ float g_attn0[(size_t)BB*INDN*DD];
__device__ float g_indB [(size_t)BB*INDN*DD];
__device__ float g_indC [(size_t)BB*INDN*DD];
__device__ float g_Q1   [(size_t)BB*LL*DD];
__device__ float g_K1   [(size_t)BB*INDN*DD];
__device__ float g_V1   [(size_t)BB*INDN*DD];
__device__ float g_qom1 [(size_t)BB*LL*16];
__device__ float g_qth1 [(size_t)BB*LL*16];
__device__ float g_kom1 [(size_t)BB*INDN*16];
__device__ float g_kth1 [(size_t)BB*INDN*16];
__device__ float g_pen[2];
__device__ float g_statM[(size_t)BB*HH*INDN];
__device__ float g_statI[(size_t)BB*HH*INDN];
// bf16 split buffers
__device__ __nv_bfloat16 g_ahi [(size_t)BB*SS*DD];
__device__ __nv_bfloat16 g_alo [(size_t)BB*SS*DD];
__device__ __nv_bfloat16 g_wThi[(size_t)DD*DD];
__device__ __nv_bfloat16 g_wTlo[(size_t)DD*DD];
__device__ __nv_bfloat16 g_qrh [(size_t)BB*LL*HH*128];
__device__ __nv_bfloat16 g_qrl [(size_t)BB*LL*HH*128];
__device__ __nv_bfloat16 g_krh [(size_t)BB*SS*HH*128];
__device__ __nv_bfloat16 g_krl [(size_t)BB*SS*HH*128];

// ---------------------------------------------------------------------------
// Packed f32x2 helpers
// ---------------------------------------------------------------------------
__device__ __forceinline__ ull pk2(float x, float y) {
    ull r;
    asm("mov.b64 %0, {%1, %2};" : "=l"(r) : "f"(x), "f"(y));
    return r;
}
__device__ __forceinline__ void fma2(ull& d, ull a, ull b) {
    asm("fma.rn.f32x2 %0, %1, %2, %0;" : "+l"(d) : "l"(a), "l"(b));
}
__device__ __forceinline__ float2 upk2(ull v) {
    float2 r;
    asm("mov.b64 {%0, %1}, %2;" : "=f"(r.x), "=f"(r.y) : "l"(v));
    return r;
}

// ---------------------------------------------------------------------------
// cp.async helpers (sm_80 baseline PTX)
// ---------------------------------------------------------------------------
__device__ __forceinline__ void cpa16(uint32_t dst, const void* src) {
    asm volatile("cp.async.cg.shared.global [%0], [%1], 16;"
                 :: "r"(dst), "l"(src) : "memory");
}
__device__ __forceinline__ void cpa16z(uint32_t dst, const void* src, bool v) {
    int sz = v ? 16 : 0;
    asm volatile("cp.async.cg.shared.global [%0], [%1], 16, %2;"
                 :: "r"(dst), "l"(src), "r"(sz) : "memory");
}
#define CPA_COMMIT asm volatile("cp.async.commit_group;" ::: "memory")
#define CPA_WAIT1  asm volatile("cp.async.wait_group 1;" ::: "memory")
#define CPA_WAIT0  asm volatile("cp.async.wait_group 0;" ::: "memory")

__device__ __forceinline__ uint32_t smem_u32(const void* p) {
    uint32_t a;
    asm("{ .reg .u64 t; cvta.to.shared.u64 t, %1; cvt.u32.u64 %0, t; }" : "=r"(a) : "l"(p));
    return a;
}

// ---------------------------------------------------------------------------
// bf16 mma helper (baseline PTX, sm_80+)
// ---------------------------------------------------------------------------
__device__ __forceinline__ void mma_bf16(float* c, const uint32_t* a, const uint32_t* b) {
    asm volatile(
        "mma.sync.aligned.m16n8k16.row.col.f32.bf16.bf16.f32 "
        "{%0,%1,%2,%3}, {%4,%5,%6,%7}, {%8,%9}, {%0,%1,%2,%3};"
        : "+f"(c[0]), "+f"(c[1]), "+f"(c[2]), "+f"(c[3])
        : "r"(a[0]), "r"(a[1]), "r"(a[2]), "r"(a[3]), "r"(b[0]), "r"(b[1]));
}

#define MMA_STAGE 40960
extern __shared__ char dynsm[];

// ---------------------------------------------------------------------------
// mma_nn_bf16: C[N,512] = (Ahi+Alo)[N,512] @ (WThi+WTlo)^T + bias
// (no CTA-count bound: 123 regs, 1 CTA/SM — forcing 2 spills and regresses)
// ---------------------------------------------------------------------------
__global__ __launch_bounds__(256) void mma_nn_bf16(
    const __nv_bfloat16* __restrict__ Ahi, const __nv_bfloat16* __restrict__ Alo,
    const __nv_bfloat16* __restrict__ Bhi, const __nv_bfloat16* __restrict__ Blo,
    const float* __restrict__ bias, float* __restrict__ C, int N)
{
    uint32_t sb = smem_u32(dynsm);
    int tid = threadIdx.x;
    int rowBase = blockIdx.y * 128, colBase = blockIdx.x * 128;
    int wid = tid >> 5, lane = tid & 31;
    int mBase = (wid >> 2) * 64, nBase = (wid & 3) * 32;

    float c[4][4][4];
#pragma unroll
    for (int ma = 0; ma < 4; ma++)
#pragma unroll
        for (int na = 0; na < 4; na++)
#pragma unroll
            for (int i = 0; i < 4; i++) c[ma][na][i] = 0.f;

    auto issue = [&](int ck, int p) {
        uint32_t base = sb + p * MMA_STAGE;
        int k0 = ck * 32;
#pragma unroll
        for (int j = 0; j < 2; j++) {
            int i = tid + j * 256;
            int row = i >> 2, seg = i & 3;
            uint32_t off = (uint32_t)(row * 20 + seg * 4) * 4;
            size_t ga = (size_t)(rowBase + row) * 512 + k0 + seg * 8;
            cpa16(base + off,         Ahi + ga);
            cpa16(base + 10240 + off, Alo + ga);
            size_t gb = (size_t)(colBase + row) * 512 + k0 + seg * 8;
            cpa16(base + 20480 + off, Bhi + gb);
            cpa16(base + 30720 + off, Blo + gb);
        }
        CPA_COMMIT;
    };

    issue(0, 0);
    for (int ck = 0; ck < 16; ck++) {
        int p = ck & 1;
        if (ck < 15) { issue(ck + 1, p ^ 1); CPA_WAIT1; } else { CPA_WAIT0; }
        __syncthreads();
        const uint32_t* AsH = (const uint32_t*)(dynsm + p * MMA_STAGE);
        const uint32_t* AsL = AsH + 2560;
        const uint32_t* BsH = AsH + 5120;
        const uint32_t* BsL = AsH + 7680;
#pragma unroll
        for (int kk = 0; kk < 16; kk += 8) {
            int kq = kk + (lane & 3);
            uint32_t bh[4][2], bl[4][2];
#pragma unroll
            for (int na = 0; na < 4; na++) {
                int n = nBase + na * 8 + (lane >> 2);
                bh[na][0] = BsH[n * 20 + kq];     bh[na][1] = BsH[n * 20 + kq + 4];
                bl[na][0] = BsL[n * 20 + kq];     bl[na][1] = BsL[n * 20 + kq + 4];
            }
#pragma unroll
            for (int ma = 0; ma < 4; ma++) {
                int r = mBase + ma * 16 + (lane >> 2);
                uint32_t ah[4], al[4];
                ah[0] = AsH[r * 20 + kq];       ah[1] = AsH[(r + 8) * 20 + kq];
                ah[2] = AsH[r * 20 + kq + 4];   ah[3] = AsH[(r + 8) * 20 + kq + 4];
                al[0] = AsL[r * 20 + kq];       al[1] = AsL[(r + 8) * 20 + kq];
                al[2] = AsL[r * 20 + kq + 4];   al[3] = AsL[(r + 8) * 20 + kq + 4];
#pragma unroll
                for (int na = 0; na < 4; na++) mma_bf16(c[ma][na], ah, bh[na]);
#pragma unroll
                for (int na = 0; na < 4; na++) mma_bf16(c[ma][na], ah, bl[na]);
#pragma unroll
                for (int na = 0; na < 4; na++) mma_bf16(c[ma][na], al, bh[na]);
            }
        }
        __syncthreads();
    }

#pragma unroll
    for (int ma = 0; ma < 4; ma++) {
        int row0 = rowBase + mBase + ma * 16 + (lane >> 2);
        int row1 = row0 + 8;
#pragma unroll
        for (int na = 0; na < 4; na++) {
            int col = colBase + nBase + na * 8 + (lane & 3) * 2;
            float b0 = bias[col], b1 = bias[col + 1];
            if (row0 < N) {
                float2 o = make_float2(c[ma][na][0] + b0, c[ma][na][1] + b1);
                *(float2*)(C + (size_t)row0 * 512 + col) = o;
            }
            if (row1 < N) {
                float2 o = make_float2(c[ma][na][2] + b0, c[ma][na][3] + b1);
                *(float2*)(C + (size_t)row1 * 512 + col) = o;
            }
        }
    }
}

// ---------------------------------------------------------------------------
// mma_nt_bf16<MAS>: scores[bh,l,s] = (1/16) Qr.Kr per (b,h), K=128.
// ---------------------------------------------------------------------------
template<int MAS>
__global__ __launch_bounds__(256) void mma_nt_bf16(
    const __nv_bfloat16* __restrict__ Qh, const __nv_bfloat16* __restrict__ Ql,
    size_t qBstride,
    const __nv_bfloat16* __restrict__ Kh, const __nv_bfloat16* __restrict__ Kl,
    float* __restrict__ scores, int Lq, int S)
{
    uint32_t sb = smem_u32(dynsm);
    int tid = threadIdx.x;
    int bh = blockIdx.z, b = bh >> 3, h = bh & 7;
    size_t aOff = (size_t)b * qBstride + (size_t)h * 128;
    size_t bOff = ((size_t)b * S * HH + h) * 128;
    float* C = scores + (size_t)bh * Lq * S;
    int lBase = blockIdx.y * 128, sBase = blockIdx.x * 128;
    int wid = tid >> 5, lane = tid & 31;
    int mBase = (wid >> 2) * (MAS * 16), nBase = (wid & 3) * 32;

    float c[MAS][4][4];
#pragma unroll
    for (int ma = 0; ma < MAS; ma++)
#pragma unroll
        for (int na = 0; na < 4; na++)
#pragma unroll
            for (int i = 0; i < 4; i++) c[ma][na][i] = 0.f;

    auto issue = [&](int ck, int p) {
        uint32_t base = sb + p * MMA_STAGE;
        int k0 = ck * 32;
#pragma unroll
        for (int j = 0; j < 2; j++) {
            int i = tid + j * 256;
            int row = i >> 2, seg = i & 3;
            uint32_t off = (uint32_t)(row * 20 + seg * 4) * 4;
            int gl = lBase + row;
            bool va = gl < Lq;
            size_t ga = aOff + (size_t)(va ? gl : 0) * 1024 + k0 + seg * 8;
            cpa16z(base + off,         Qh + ga, va);
            cpa16z(base + 10240 + off, Ql + ga, va);
            int gs = sBase + row;
            bool vb = gs < S;
            size_t gb = bOff + (size_t)(vb ? gs : 0) * 1024 + k0 + seg * 8;
            cpa16z(base + 20480 + off, Kh + gb, vb);
            cpa16z(base + 30720 + off, Kl + gb, vb);
        }
        CPA_COMMIT;
    };

    issue(0, 0);
    for (int ck = 0; ck < 4; ck++) {
        int p = ck & 1;
        if (ck < 3) { issue(ck + 1, p ^ 1); CPA_WAIT1; } else { CPA_WAIT0; }
        __syncthreads();
        const uint32_t* AsH = (const uint32_t*)(dynsm + p * MMA_STAGE);
        const uint32_t* AsL = AsH + 2560;
        const uint32_t* BsH = AsH + 5120;
        const uint32_t* BsL = AsH + 7680;
#pragma unroll
        for (int kk = 0; kk < 16; kk += 8) {
            int kq = kk + (lane & 3);
            uint32_t bhf[4][2], blf[4][2];
#pragma unroll
            for (int na = 0; na < 4; na++) {
                int n = nBase + na * 8 + (lane >> 2);
                bhf[na][0] = BsH[n * 20 + kq];  bhf[na][1] = BsH[n * 20 + kq + 4];
                blf[na][0] = BsL[n * 20 + kq];  blf[na][1] = BsL[n * 20 + kq + 4];
            }
#pragma unroll
            for (int ma = 0; ma < MAS; ma++) {
                int r = mBase + ma * 16 + (lane >> 2);
                uint32_t ah[4], al[4];
                ah[0] = AsH[r * 20 + kq];       ah[1] = AsH[(r + 8) * 20 + kq];
                ah[2] = AsH[r * 20 + kq + 4];   ah[3] = AsH[(r + 8) * 20 + kq + 4];
                al[0] = AsL[r * 20 + kq];       al[1] = AsL[(r + 8) * 20 + kq];
                al[2] = AsL[r * 20 + kq + 4];   al[3] = AsL[(r + 8) * 20 + kq + 4];
#pragma unroll
                for (int na = 0; na < 4; na++) mma_bf16(c[ma][na], ah, bhf[na]);
#pragma unroll
                for (int na = 0; na < 4; na++) mma_bf16(c[ma][na], ah, blf[na]);
#pragma unroll
                for (int na = 0; na < 4; na++) mma_bf16(c[ma][na], al, bhf[na]);
            }
        }
        __syncthreads();
    }

#pragma unroll
    for (int ma = 0; ma < MAS; ma++) {
        int l0 = lBase + mBase + ma * 16 + (lane >> 2);
        int l1 = l0 + 8;
#pragma unroll
        for (int na = 0; na < 4; na++) {
            int s = sBase + nBase + na * 8 + (lane & 3) * 2;
            if (s + 1 < S) {
                if (l0 < Lq) {
                    float2 o = make_float2(c[ma][na][0] * 0.0625f, c[ma][na][1] * 0.0625f);
                    *(float2*)(C + (size_t)l0 * S + s) = o;
                }
                if (l1 < Lq) {
                    float2 o = make_float2(c[ma][na][2] * 0.0625f, c[ma][na][3] * 0.0625f);
                    *(float2*)(C + (size_t)l1 * S + s) = o;
                }
            } else if (s < S) {
                if (l0 < Lq) C[(size_t)l0 * S + s] = c[ma][na][0] * 0.0625f;
                if (l1 < Lq) C[(size_t)l1 * S + s] = c[ma][na][2] * 0.0625f;
            }
        }
    }
}

// ---------------------------------------------------------------------------
// attn1_fused: layer-1 scores (mma, 3-term) + softmax + AV in one block.
// Output written directly as bf16 hi/lo (feeds the final Wo GEMM).
// ---------------------------------------------------------------------------
#define AT_QH 0
#define AT_QL 34816
#define AT_KH 69632
#define AT_KL 95744
#define AT_V  121856
#define AT_PS 146432
#define AT_SMEM 197632

__global__ __launch_bounds__(256) void attn1_fused(
    const __nv_bfloat16* __restrict__ Qh, const __nv_bfloat16* __restrict__ Ql,
    const __nv_bfloat16* __restrict__ Kh, const __nv_bfloat16* __restrict__ Kl,
    const float* __restrict__ V,
    __nv_bfloat16* __restrict__ Oh, __nv_bfloat16* __restrict__ Ol)
{
    uint32_t sb = smem_u32(dynsm);
    int tid = threadIdx.x, wid = tid >> 5, lane = tid & 31;
    int lBase = blockIdx.x * 128, h = blockIdx.y, b = blockIdx.z;

#pragma unroll
    for (int i = 0; i < 8; i++) {
        int seg = tid + i * 256;
        int row = seg >> 4, sg = seg & 15;
        size_t g = ((size_t)(b * LL + lBase + row) * HH + h) * 128 + sg * 8;
        uint32_t so = (uint32_t)(row * 272 + sg * 16);
        cpa16(sb + AT_QH + so, Qh + g);
        cpa16(sb + AT_QL + so, Ql + g);
    }
#pragma unroll
    for (int i = 0; i < 6; i++) {
        int seg = tid + i * 256;
        int row = seg >> 4, sg = seg & 15;
        size_t g = ((size_t)(b * INDN + row) * HH + h) * 128 + sg * 8;
        uint32_t so = (uint32_t)(row * 272 + sg * 16);
        cpa16(sb + AT_KH + so, Kh + g);
        cpa16(sb + AT_KL + so, Kl + g);
        size_t gv = (size_t)(b * INDN + row) * 512 + h * 64 + sg * 4;
        cpa16(sb + AT_V + (uint32_t)(row * 256 + sg * 16), V + gv);
    }
    CPA_COMMIT; CPA_WAIT0;
    __syncthreads();

    int mBase = wid * 16;
    float c[12][4];
#pragma unroll
    for (int nt = 0; nt < 12; nt++)
#pragma unroll
        for (int i = 0; i < 4; i++) c[nt][i] = 0.f;

    int r0 = mBase + (lane >> 2);
#pragma unroll
    for (int kk = 0; kk < 8; kk++) {
        int kq4 = (kk * 8 + (lane & 3)) * 4;
        uint32_t ah[4], al[4];
        ah[0] = *(const uint32_t*)(dynsm + AT_QH + r0 * 272 + kq4);
        ah[1] = *(const uint32_t*)(dynsm + AT_QH + (r0 + 8) * 272 + kq4);
        ah[2] = *(const uint32_t*)(dynsm + AT_QH + r0 * 272 + kq4 + 16);
        ah[3] = *(const uint32_t*)(dynsm + AT_QH + (r0 + 8) * 272 + kq4 + 16);
        al[0] = *(const uint32_t*)(dynsm + AT_QL + r0 * 272 + kq4);
        al[1] = *(const uint32_t*)(dynsm + AT_QL + (r0 + 8) * 272 + kq4);
        al[2] = *(const uint32_t*)(dynsm + AT_QL + r0 * 272 + kq4 + 16);
        al[3] = *(const uint32_t*)(dynsm + AT_QL + (r0 + 8) * 272 + kq4 + 16);
        uint32_t bhf[12][2], blf[12][2];
#pragma unroll
        for (int nt = 0; nt < 12; nt++) {
            int n = nt * 8 + (lane >> 2);
            bhf[nt][0] = *(const uint32_t*)(dynsm + AT_KH + n * 272 + kq4);
            bhf[nt][1] = *(const uint32_t*)(dynsm + AT_KH + n * 272 + kq4 + 16);
            blf[nt][0] = *(const uint32_t*)(dynsm + AT_KL + n * 272 + kq4);
            blf[nt][1] = *(const uint32_t*)(dynsm + AT_KL + n * 272 + kq4 + 16);
        }
#pragma unroll
        for (int nt = 0; nt < 12; nt++) mma_bf16(c[nt], ah, bhf[nt]);
#pragma unroll
        for (int nt = 0; nt < 12; nt++) mma_bf16(c[nt], ah, blf[nt]);
#pragma unroll
        for (int nt = 0; nt < 12; nt++) mma_bf16(c[nt], al, bhf[nt]);
    }

#pragma unroll
    for (int nt = 0; nt < 12; nt++) {
        int s = nt * 8 + (lane & 3) * 2;
        *(float2*)(dynsm + AT_PS + r0 * 400 + s * 4) =
            make_float2(c[nt][0] * 0.0625f, c[nt][1] * 0.0625f);
        *(float2*)(dynsm + AT_PS + (r0 + 8) * 400 + s * 4) =
            make_float2(c[nt][2] * 0.0625f, c[nt][3] * 0.0625f);
    }
    __syncthreads();

    const float* Vsm = (const float*)(dynsm + AT_V);
#pragma unroll 4
    for (int rr = 0; rr < 16; rr++) {
        int row = mBase + rr;
        const float* PsRow = (const float*)(dynsm + AT_PS + row * 400);
        float pr[3];
        pr[0] = PsRow[lane]; pr[1] = PsRow[lane + 32]; pr[2] = PsRow[lane + 64];
        float m = fmaxf(pr[0], fmaxf(pr[1], pr[2]));
#pragma unroll
        for (int off = 16; off > 0; off >>= 1)
            m = fmaxf(m, __shfl_xor_sync(0xffffffffu, m, off));
        pr[0] = __expf(pr[0] - m); pr[1] = __expf(pr[1] - m); pr[2] = __expf(pr[2] - m);
        float ssum = pr[0] + pr[1] + pr[2];
#pragma unroll
        for (int off = 16; off > 0; off >>= 1)
            ssum += __shfl_xor_sync(0xffffffffu, ssum, off);
        float inv = 1.f / ssum;
        float a0 = 0.f, a1 = 0.f;
#pragma unroll
        for (int j = 0; j < 3; j++)
#pragma unroll
            for (int sl = 0; sl < 32; sl++) {
                float ps = __shfl_sync(0xffffffffu, pr[j], sl);
                int s = j * 32 + sl;
                a0 = fmaf(ps, Vsm[s * 64 + lane], a0);
                a1 = fmaf(ps, Vsm[s * 64 + lane + 32], a1);
            }
        float r0v = a0 * inv, r1v = a1 * inv;
        size_t ob = ((size_t)(b * LL + lBase + row)) * 512 + h * 64;
        __nv_bfloat16 h0 = __float2bfloat16(r0v);
        __nv_bfloat16 h1 = __float2bfloat16(r1v);
        Oh[ob + lane]      = h0;
        Oh[ob + lane + 32] = h1;
        Ol[ob + lane]      = __float2bfloat16(r0v - __bfloat162float(h0));
        Ol[ob + lane + 32] = __float2bfloat16(r1v - __bfloat162float(h1));
    }
}

// ---------------------------------------------------------------------------
// Split fp32 -> (hi, lo) bf16
// ---------------------------------------------------------------------------
__global__ __launch_bounds__(256) void split_f32(
    const float* __restrict__ x, __nv_bfloat16* __restrict__ hi,
    __nv_bfloat16* __restrict__ lo, int n4)
{
    for (int i = blockIdx.x * 256 + threadIdx.x; i < n4; i += gridDim.x * 256) {
        float4 v = ((const float4*)x)[i];
        __nv_bfloat16 h0 = __float2bfloat16(v.x);
        __nv_bfloat16 h1 = __float2bfloat16(v.y);
        __nv_bfloat16 h2 = __float2bfloat16(v.z);
        __nv_bfloat16 h3 = __float2bfloat16(v.w);
        __nv_bfloat162* hp = (__nv_bfloat162*)hi;
        __nv_bfloat162* lp = (__nv_bfloat162*)lo;
        hp[2*i]   = __nv_bfloat162(h0, h1);
        hp[2*i+1] = __nv_bfloat162(h2, h3);
        lp[2*i]   = __nv_bfloat162(__float2bfloat16(v.x - __bfloat162float(h0)),
                                   __float2bfloat16(v.y - __bfloat162float(h1)));
        lp[2*i+1] = __nv_bfloat162(__float2bfloat16(v.z - __bfloat162float(h2)),
                                   __float2bfloat16(v.w - __bfloat162float(h3)));
    }
}

// ---------------------------------------------------------------------------
// Split + transpose W[512,512] -> WT hi/lo
// ---------------------------------------------------------------------------
__global__ __launch_bounds__(256) void split_wT(
    const float* __restrict__ W, __nv_bfloat16* __restrict__ hiT,
    __nv_bfloat16* __restrict__ loT)
{
    __shared__ float t[32][33];
    int bn = blockIdx.x * 32;
    int bk = blockIdx.y * 32;
    int tx = threadIdx.x & 31, ty = threadIdx.x >> 5;
    for (int r = ty; r < 32; r += 8)
        t[r][tx] = W[(size_t)(bk + r) * 512 + bn + tx];
    __syncthreads();
    for (int r = ty; r < 32; r += 8) {
        float v = t[tx][r];
        __nv_bfloat16 h = __float2bfloat16(v);
        size_t o = (size_t)(bn + r) * 512 + bk + tx;
        hiT[o] = h;
        loT[o] = __float2bfloat16(v - __bfloat162float(h));
    }
}

// ---------------------------------------------------------------------------
// FFMA2 GEMM (NN) for small exact-fp32 GEMMs
// ---------------------------------------------------------------------------
__global__ __launch_bounds__(256, 2) void gemm_nn(
    const float* __restrict__ A, const float* __restrict__ W,
    const float* __restrict__ bias, float* __restrict__ C, int N, int P)
{
    __shared__ float As[16][132];
    __shared__ float Bs[16][132];
    int tid = threadIdx.x;
    int rowBase = blockIdx.y * 128;
    int colBase = blockIdx.x * 128;
    int ty = tid >> 4, tx = tid & 15;

    ull acc[4][8];
#pragma unroll
    for (int p = 0; p < 4; p++)
#pragma unroll
        for (int j = 0; j < 8; j++) acc[p][j] = 0ull;

    int aRow = tid >> 2;
    int aK   = (tid & 3) * 4;
    int bK   = tid >> 4;
    int bCol = (tid & 15) * 4;
    bool v0 = (rowBase + aRow) < N;
    bool v1 = (rowBase + aRow + 64) < N;
    const float* Ap0 = A + (size_t)(rowBase + aRow) * 512 + aK;
    const float* Ap1 = Ap0 + (size_t)64 * 512;
    const float* Wp  = W + (size_t)bK * P + colBase + bCol;

    for (int k0 = 0; k0 < 512; k0 += 16) {
        float4 a0 = v0 ? *(const float4*)(Ap0 + k0) : make_float4(0.f,0.f,0.f,0.f);
        float4 a1 = v1 ? *(const float4*)(Ap1 + k0) : make_float4(0.f,0.f,0.f,0.f);
        As[aK+0][aRow] = a0.x; As[aK+1][aRow] = a0.y;
        As[aK+2][aRow] = a0.z; As[aK+3][aRow] = a0.w;
        As[aK+0][aRow+64] = a1.x; As[aK+1][aRow+64] = a1.y;
        As[aK+2][aRow+64] = a1.z; As[aK+3][aRow+64] = a1.w;
        float4 b0 = *(const float4*)(Wp + (size_t)k0 * P);
        float4 b1 = *(const float4*)(Wp + (size_t)k0 * P + 64);
        *(float4*)&Bs[bK][bCol]      = b0;
        *(float4*)&Bs[bK][bCol + 64] = b1;
        __syncthreads();
#pragma unroll
        for (int k = 0; k < 16; k++) {
            float4 av0 = *(const float4*)&As[k][ty*4];
            float4 av1 = *(const float4*)&As[k][64 + ty*4];
            float4 bv0 = *(const float4*)&Bs[k][tx*4];
            float4 bv1 = *(const float4*)&Bs[k][64 + tx*4];
            ull ap[4];
            ap[0] = pk2(av0.x, av0.y); ap[1] = pk2(av0.z, av0.w);
            ap[2] = pk2(av1.x, av1.y); ap[3] = pk2(av1.z, av1.w);
            ull bd[8];
            bd[0] = pk2(bv0.x, bv0.x); bd[1] = pk2(bv0.y, bv0.y);
            bd[2] = pk2(bv0.z, bv0.z); bd[3] = pk2(bv0.w, bv0.w);
            bd[4] = pk2(bv1.x, bv1.x); bd[5] = pk2(bv1.y, bv1.y);
            bd[6] = pk2(bv1.z, bv1.z); bd[7] = pk2(bv1.w, bv1.w);
#pragma unroll
            for (int p = 0; p < 4; p++)
#pragma unroll
                for (int j = 0; j < 8; j++)
                    fma2(acc[p][j], ap[p], bd[j]);
        }
        __syncthreads();
    }

#pragma unroll
    for (int p = 0; p < 4; p++) {
        int row = rowBase + ((p < 2) ? (ty*4 + p*2) : (64 + ty*4 + (p-2)*2));
#pragma unroll
        for (int j = 0; j < 8; j++) {
            int col = colBase + ((j < 4) ? (tx*4 + j) : (64 + tx*4 + (j-4)));
            float2 r = upk2(acc[p][j]);
            float bb = bias[col];
            if (row < N)     C[(size_t)row * P + col]     = r.x + bb;
            if (row + 1 < N) C[(size_t)(row+1) * P + col] = r.y + bb;
        }
    }
}

// ---------------------------------------------------------------------------
// Fused omega/theta heads
// ---------------------------------------------------------------------------
__global__ __launch_bounds__(256) void gemm_omth(
    const float* __restrict__ A,
    const float* __restrict__ Wom, const float* __restrict__ bom,
    const float* __restrict__ Wth, const float* __restrict__ bth,
    float* __restrict__ Com, float* __restrict__ Cth, int N)
{
    __shared__ float As[16][68];
    __shared__ float Ws[16][34];
    int tid = threadIdx.x;
    int rowBase = blockIdx.x * 64;
    int ty = tid >> 4, tx = tid & 15;
    float acc[4][2] = {{0.f,0.f},{0.f,0.f},{0.f,0.f},{0.f,0.f}};

    int aRow = tid >> 2;
    int aK   = (tid & 3) * 4;
    int wK   = tid >> 4;
    int wC   = tid & 15;
    bool av = (rowBase + aRow) < N;
    const float* Ap = A + (size_t)(rowBase + aRow) * 512 + aK;

    for (int k0 = 0; k0 < 512; k0 += 16) {
        float4 a = av ? *(const float4*)(Ap + k0) : make_float4(0.f,0.f,0.f,0.f);
        As[aK+0][aRow] = a.x; As[aK+1][aRow] = a.y;
        As[aK+2][aRow] = a.z; As[aK+3][aRow] = a.w;
        Ws[wK][wC]      = Wom[(size_t)(k0 + wK) * 16 + wC];
        Ws[wK][16 + wC] = Wth[(size_t)(k0 + wK) * 16 + wC];
        __syncthreads();
#pragma unroll
        for (int k = 0; k < 16; k++) {
            float4 avv = *(const float4*)&As[k][ty*4];
            float w0 = Ws[k][tx], w1 = Ws[k][16 + tx];
            acc[0][0] = fmaf(avv.x, w0, acc[0][0]); acc[0][1] = fmaf(avv.x, w1, acc[0][1]);
            acc[1][0] = fmaf(avv.y, w0, acc[1][0]); acc[1][1] = fmaf(avv.y, w1, acc[1][1]);
            acc[2][0] = fmaf(avv.z, w0, acc[2][0]); acc[2][1] = fmaf(avv.z, w1, acc[2][1]);
            acc[3][0] = fmaf(avv.w, w0, acc[3][0]); acc[3][1] = fmaf(avv.w, w1, acc[3][1]);
        }
        __syncthreads();
    }
#pragma unroll
    for (int i = 0; i < 4; i++) {
        int row = rowBase + ty*4 + i;
        if (row >= N) continue;
        Com[(size_t)row * 16 + tx] = fmaxf(acc[i][0] + bom[tx], 0.f);
        Cth[(size_t)row * 16 + tx] = tanhf(acc[i][1] + bth[tx]) * PI_F;
    }
}

// ---------------------------------------------------------------------------
// Rotation builders -> bf16 hi/lo
// ---------------------------------------------------------------------------
__device__ __forceinline__ void wr_split(__nv_bfloat16* hi, __nv_bfloat16* lo,
                                         int idx, float v) {
    __nv_bfloat16 h = __float2bfloat16(v);
    hi[idx] = h;
    lo[idx] = __float2bfloat16(v - __bfloat162float(h));
}

__global__ void build_qr(const float* __restrict__ Q, const float* __restrict__ om,
                         const float* __restrict__ th,
                         __nv_bfloat16* __restrict__ Qh, __nv_bfloat16* __restrict__ Ql,
                         int seq, float invSeq)
{
    int row = blockIdx.x;
    int tid = threadIdx.x;
    int h = tid >> 5, m = (tid >> 4) & 1, i = tid & 15;
    float pos = (float)(row % seq) * invSeq;
    int oi = row * 16 + h * 2 + m;
    float ang = fmaf(om[oi], pos, th[oi]);
    float sn, cs; sincosf(ang, &sn, &cs);
    const float* q = Q + (size_t)row * 512 + h * 64;
    float q0 = q[i], q1 = q[16+i], q2 = q[32+i], q3 = q[48+i];
    int o = ((row * HH + h) * 128) + m * 64;
    wr_split(Qh, Ql, o + i,      q0*cs - q1*sn);
    wr_split(Qh, Ql, o + 16 + i, q1*cs + q0*sn);
    wr_split(Qh, Ql, o + 32 + i, q2*cs + q3*sn);
    wr_split(Qh, Ql, o + 48 + i, q3*cs - q2*sn);
}

__global__ void build_kr(const float* __restrict__ K, const float* __restrict__ om,
                         const float* __restrict__ th,
                         __nv_bfloat16* __restrict__ Kh, __nv_bfloat16* __restrict__ Kl,
                         int seq, float invSeq)
{
    int row = blockIdx.x;
    int tid = threadIdx.x;
    int h = tid >> 5, m = (tid >> 4) & 1, i = tid & 15;
    float pos = (float)(row % seq) * invSeq;
    int oi = row * 16 + h * 2 + m;
    float ang = fmaf(om[oi], pos, th[oi]);
    float sn, cs; sincosf(ang, &sn, &cs);
    const float* k = K + (size_t)row * 512 + h * 64;
    float k0 = k[i], k1 = k[16+i], k2 = k[32+i], k3 = k[48+i];
    int o = ((row * HH + h) * 128) + m * 64;
    wr_split(Kh, Kl, o + i,      k0*cs - k2*sn);
    wr_split(Kh, Kl, o + 16 + i, k1*cs - k3*sn);
    wr_split(Kh, Kl, o + 32 + i, k2*cs + k0*sn);
    wr_split(Kh, Kl, o + 48 + i, k3*cs + k1*sn);
}

// ---------------------------------------------------------------------------
// row_stats: per-row max and 1/sum(exp) for layer-0 softmax
// ---------------------------------------------------------------------------
__global__ __launch_bounds__(256) void row_stats(
    const float* __restrict__ scores, float* __restrict__ M, float* __restrict__ I)
{
    int row = blockIdx.x * 8 + (threadIdx.x >> 5);
    int lane = threadIdx.x & 31;
    const float* r = scores + (size_t)row * SS;
    float m = -3.4e38f;
    for (int i = lane; i < SS; i += 32) m = fmaxf(m, r[i]);
#pragma unroll
    for (int o = 16; o; o >>= 1) m = fmaxf(m, __shfl_xor_sync(0xffffffffu, m, o));
    float s = 0.f;
    for (int i = lane; i < SS; i += 32) s += __expf(r[i] - m);
#pragma unroll
    for (int o = 16; o; o >>= 1) s += __shfl_xor_sync(0xffffffffu, s, o);
    if (lane == 0) { M[row] = m; I[row] = 1.f / s; }
}

// ---------------------------------------------------------------------------
// av48: tiled softmax-weighted AV for layer 0
// ---------------------------------------------------------------------------
__global__ __launch_bounds__(256) void av48(
    const float* __restrict__ scores, const float* __restrict__ V,
    const float* __restrict__ M, const float* __restrict__ I,
    float* __restrict__ out)
{
    __shared__ float Vs[64][64];
    __shared__ float Ps[48][65];
    __shared__ float Ms[48], Is[48];
    int h = blockIdx.y, b = blockIdx.z;
    int l0 = blockIdx.x * 48;
    int bh = b * HH + h;
    int tid = threadIdx.x;
    int eg = tid & 15;
    int rg = tid >> 4;
    if (tid < 48) {
        Ms[tid] = M[bh * INDN + l0 + tid];
        Is[tid] = I[bh * INDN + l0 + tid];
    }
    const float* S0 = scores + ((size_t)bh * INDN + l0) * SS;
    const float* Vb = V + ((size_t)b * SS) * 512 + h * 64;
    __syncthreads();
    ull acc[3][2] = {{0ull,0ull},{0ull,0ull},{0ull,0ull}};
    for (int s0 = 0; s0 < SS; s0 += 64) {
#pragma unroll
        for (int i = 0; i < 4; i++) {
            int s = (tid >> 4) + i * 16;
            *(float4*)&Vs[s][eg * 4] = *(const float4*)&Vb[(size_t)(s0 + s) * 512 + eg * 4];
        }
#pragma unroll
        for (int i = 0; i < 3; i++) {
            int idx = tid + i * 256;
            int r = idx >> 4, sseg = idx & 15;
            float4 v = *(const float4*)&S0[(size_t)r * SS + s0 + sseg * 4];
            float m = Ms[r];
            Ps[r][sseg*4+0] = __expf(v.x - m);
            Ps[r][sseg*4+1] = __expf(v.y - m);
            Ps[r][sseg*4+2] = __expf(v.z - m);
            Ps[r][sseg*4+3] = __expf(v.w - m);
        }
        __syncthreads();
#pragma unroll 4
        for (int s = 0; s < 64; s++) {
            float4 v = *(const float4*)&Vs[s][eg * 4];
            ull vA = pk2(v.x, v.y), vB = pk2(v.z, v.w);
#pragma unroll
            for (int j = 0; j < 3; j++) {
                float p = Ps[rg * 3 + j][s];
                ull pp = pk2(p, p);
                fma2(acc[j][0], pp, vA);
                fma2(acc[j][1], pp, vB);
            }
        }
        __syncthreads();
    }
#pragma unroll
    for (int j = 0; j < 3; j++) {
        int l = l0 + rg * 3 + j;
        float inv = Is[rg * 3 + j];
        float2 a = upk2(acc[j][0]), bq = upk2(acc[j][1]);
        float* o = out + ((size_t)b * INDN + l) * 512 + h * 64 + eg * 4;
        *(float4*)o = make_float4(a.x * inv, a.y * inv, bq.x * inv, bq.y * inv);
    }
}

// ---------------------------------------------------------------------------
// Trend norm
// ---------------------------------------------------------------------------
__global__ __launch_bounds__(256) void trend_norm(
    const float* __restrict__ x, const float* __restrict__ gm,
    const float* __restrict__ bt, float* __restrict__ y)
{
    __shared__ float seas[512];
    __shared__ float trend[512];
    __shared__ float red[256];
    int b = blockIdx.y, t = blockIdx.x, tid = threadIdx.x;
    const float* xb = x + (size_t)b * INDN * 512;
    float ls = 0.f, ls2 = 0.f;
    for (int d = tid; d < 512; d += 256) {
        float tr = 0.f;
#pragma unroll
        for (int j = -12; j <= 12; j++) {
            int tt = t + j;
            tt = tt < 0 ? 0 : (tt > INDN-1 ? INDN-1 : tt);
            tr += xb[(size_t)tt * 512 + d];
        }
        tr *= (1.0f / 25.0f);
        float sv = xb[(size_t)t * 512 + d] - tr;
        seas[d] = sv; trend[d] = tr;
        ls += sv; ls2 += sv * sv;
    }
    red[tid] = ls; __syncthreads();
    for (int off = 128; off > 0; off >>= 1) { if (tid < off) red[tid] += red[tid+off]; __syncthreads(); }
    float mu = red[0] * (1.f/512.f); __syncthreads();
    red[tid] = ls2; __syncthreads();
    for (int off = 128; off > 0; off >>= 1) { if (tid < off) red[tid] += red[tid+off]; __syncthreads(); }
    float var = red[0] * (1.f/512.f) - mu*mu;
    float rs = rsqrtf(var + 1e-5f);
    for (int d = tid; d < 512; d += 256)
        y[((size_t)b*INDN + t) * 512 + d] = (seas[d] - mu) * rs * gm[d] + bt[d] + trend[d];
}

// ---------------------------------------------------------------------------
// Penalties
// ---------------------------------------------------------------------------
__global__ void zero_pen() { g_pen[0] = 0.f; g_pen[1] = 0.f; }

__global__ __launch_bounds__(256) void penalty_kernel(
    const float* __restrict__ om, const float* __restrict__ th,
    int total, int seq, float scale)
{
    float omp = 0.f, thp = 0.f;
    for (int idx = blockIdx.x * 256 + threadIdx.x; idx < total; idx += gridDim.x * 256) {
        int n = idx >> 4;
        int sIn = n % seq;
        float t = th[idx]; thp += t * t;
        if (sIn < seq - 1) { float d = om[idx + 16] - om[idx]; omp += d * d; }
    }
#pragma unroll
    for (int o = 16; o > 0; o >>= 1) {
        omp += __shfl_down_sync(0xffffffffu, omp, o);
        thp += __shfl_down_sync(0xffffffffu, thp, o);
    }
    __shared__ float sho[8], sht[8];
    int wid = threadIdx.x >> 5, lid = threadIdx.x & 31;
    if (lid == 0) { sho[wid] = omp; sht[wid] = thp; }
    __syncthreads();
    if (threadIdx.x == 0) {
        float so = 0.f, st = 0.f;
        for (int w = 0; w < 8; w++) { so += sho[w]; st += sht[w]; }
        atomicAdd(&g_pen[0], so * scale);
        atomicAdd(&g_pen[1], st * scale);
    }
}

__global__ void finalize_kernel(float* out, int out_size)
{
    if (out_size >= BLD + 2) {
        out[BLD]     = g_pen[0];
        out[BLD + 1] = g_pen[1];
    }
}

// ---------------------------------------------------------------------------
// Host launcher (sequential)
// ---------------------------------------------------------------------------
#define SYMADDR(p, s) do { void* _t = nullptr; cudaGetSymbolAddress(&_t, s); (p) = decltype(p)(_t); } while (0)

extern "C" void kernel_launch(void* const* d_in, const int* in_sizes, int n_in,
                              void* d_out, int out_size)
{
    (void)in_sizes; (void)n_in;
    const float* queries = (const float*)d_in[0];
    const float* keys    = (const float*)d_in[1];
    const float* values  = (const float*)d_in[2];
    const float* Wq  = (const float*)d_in[3];
    const float* bq  = (const float*)d_in[4];
    const float* Wk  = (const float*)d_in[5];
    const float* bk  = (const float*)d_in[6];
    const float* Wv  = (const float*)d_in[7];
    const float* bv  = (const float*)d_in[8];
    const float* Wqo = (const float*)d_in[9];
    const float* bqo = (const float*)d_in[10];
    const float* Wko = (const float*)d_in[11];
    const float* bko = (const float*)d_in[12];
    const float* Wqt = (const float*)d_in[13];
    const float* bqt = (const float*)d_in[14];
    const float* Wkt = (const float*)d_in[15];
    const float* bkt = (const float*)d_in[16];
    const float* Wo  = (const float*)d_in[17];
    const float* bo  = (const float*)d_in[18];
    const float* Ibuf = (const float*)d_in[19];
    const float* ln_g = (const float*)d_in[20];
    const float* ln_b = (const float*)d_in[21];
    float* out = (float*)d_out;

    const int NBS = BB * SS;      // 24576
    const int NBI = BB * INDN;    // 768
    const int W2  = 512 * 512;
    const int W2S = 512 * 16;
    const int N4  = NBS * 512 / 4;
    const int MMA_DSM = 2 * MMA_STAGE;  // 81920

    float *pK0, *pV0, *pQ0, *pkom0, *pkth0, *pqom0, *pqth0, *pScores;
    float *pAttn0, *pIndB, *pIndC, *pQ1, *pK1, *pV1, *pqom1, *pqth1, *pkom1, *pkth1;
    float *pStatM, *pStatI;
    __nv_bfloat16 *pAhi, *pAlo, *pWThi, *pWTlo, *pQrh, *pQrl, *pKrh, *pKrl;
    SYMADDR(pK0, g_K0);     SYMADDR(pV0, g_V0);     SYMADDR(pQ0, g_Q0);
    SYMADDR(pkom0, g_kom0); SYMADDR(pkth0, g_kth0);
    SYMADDR(pqom0, g_qom0); SYMADDR(pqth0, g_qth0);
    SYMADDR(pScores, g_scores);
    SYMADDR(pAttn0, g_attn0); SYMADDR(pIndB, g_indB); SYMADDR(pIndC, g_indC);
    SYMADDR(pQ1, g_Q1);     SYMADDR(pK1, g_K1);     SYMADDR(pV1, g_V1);
    SYMADDR(pqom1, g_qom1); SYMADDR(pqth1, g_qth1);
    SYMADDR(pkom1, g_kom1); SYMADDR(pkth1, g_kth1);
    SYMADDR(pStatM, g_statM); SYMADDR(pStatI, g_statI);
    SYMADDR(pAhi, g_ahi);   SYMADDR(pAlo, g_alo);
    SYMADDR(pWThi, g_wThi); SYMADDR(pWTlo, g_wTlo);
    SYMADDR(pQrh, g_qrh);   SYMADDR(pQrl, g_qrl);
    SYMADDR(pKrh, g_krh);   SYMADDR(pKrl, g_krl);

    cudaFuncSetAttribute(mma_nn_bf16, cudaFuncAttributeMaxDynamicSharedMemorySize, MMA_DSM);
    cudaFuncSetAttribute(mma_nt_bf16<3>, cudaFuncAttributeMaxDynamicSharedMemorySize, MMA_DSM);
    cudaFuncSetAttribute(attn1_fused, cudaFuncAttributeMaxDynamicSharedMemorySize, AT_SMEM);

    dim3 gBig(4, NBS / 128);
    dim3 gWT(16, 16);

    // ------------------------ Layer 0 (inducings x keys/values) -------------
    split_f32<<<2048, 256>>>(keys, pAhi, pAlo, N4);
    split_wT<<<gWT, 256>>>(Wk, pWThi, pWTlo);
    mma_nn_bf16<<<gBig, 256, MMA_DSM>>>(pAhi, pAlo, pWThi, pWTlo, bk, pK0, NBS);

    split_f32<<<2048, 256>>>(values, pAhi, pAlo, N4);
    split_wT<<<gWT, 256>>>(Wv, pWThi, pWTlo);
    mma_nn_bf16<<<gBig, 256, MMA_DSM>>>(pAhi, pAlo, pWThi, pWTlo, bv, pV0, NBS);

    gemm_nn<<<dim3(4, 1), 256>>>(Ibuf, Wq, bq, pQ0, INDN, 512);

    gemm_omth<<<NBS/64, 256>>>(keys, Wko, bko, Wkt, bkt, pkom0, pkth0, NBS);
    gemm_omth<<<(INDN+63)/64, 256>>>(Ibuf, Wqo, bqo, Wqt, bqt, pqom0, pqth0, INDN);

    zero_pen<<<1, 1>>>();
    penalty_kernel<<<6, 256>>>(pqom0, pqth0, INDN*16, INDN, (float)BB);
    penalty_kernel<<<1024, 256>>>(pkom0, pkth0, NBS*16, SS, 1.f);

    build_qr<<<INDN, 256>>>(pQ0, pqom0, pqth0, pQrh, pQrl, INDN, 1.f/INDN);
    build_kr<<<NBS,  256>>>(pK0, pkom0, pkth0, pKrh, pKrl, SS,   1.f/SS);

    mma_nt_bf16<3><<<dim3(SS/128, 1, BB*HH), 256, MMA_DSM>>>(pQrh, pQrl, (size_t)0,
                                                             pKrh, pKrl, pScores, INDN, SS);
    row_stats<<<BB*HH*INDN/8, 256>>>(pScores, pStatM, pStatI);
    av48<<<dim3(2, HH, BB), 256>>>(pScores, pV0, pStatM, pStatI, pAttn0);

    gemm_nn<<<dim3(4, 6), 256>>>(pAttn0, Wo, bo, pIndB, NBI, 512);
    trend_norm<<<dim3(INDN, BB), 256>>>(pIndB, ln_g, ln_b, pIndC);

    // ------------------------ Layer 1 (queries x inducings) -----------------
    split_f32<<<2048, 256>>>(queries, pAhi, pAlo, N4);
    split_wT<<<gWT, 256>>>(Wq + W2, pWThi, pWTlo);
    mma_nn_bf16<<<gBig, 256, MMA_DSM>>>(pAhi, pAlo, pWThi, pWTlo, bq + 512, pQ1, NBS);

    gemm_nn<<<dim3(4, 6), 256>>>(pIndC, Wk + W2, bk + 512, pK1, NBI, 512);
    gemm_nn<<<dim3(4, 6), 256>>>(pIndC, Wv + W2, bv + 512, pV1, NBI, 512);

    gemm_omth<<<NBS/64, 256>>>(queries, Wqo + W2S, bqo + 16, Wqt + W2S, bqt + 16,
                               pqom1, pqth1, NBS);
    gemm_omth<<<NBI/64, 256>>>(pIndC, Wko + W2S, bko + 16, Wkt + W2S, bkt + 16,
                               pkom1, pkth1, NBI);

    penalty_kernel<<<1024, 256>>>(pqom1, pqth1, NBS*16, LL, 1.f);
    penalty_kernel<<<48, 256>>>(pkom1, pkth1, NBI*16, INDN, 1.f);

    build_qr<<<NBS, 256>>>(pQ1, pqom1, pqth1, pQrh, pQrl, LL,   1.f/LL);
    build_kr<<<NBI, 256>>>(pK1, pkom1, pkth1, pKrh, pKrl, INDN, 1.f/INDN);

    // fused attention writes bf16 hi/lo directly into the final-GEMM A buffers
    attn1_fused<<<dim3(LL/128, HH, BB), 256, AT_SMEM>>>(pQrh, pQrl, pKrh, pKrl,
                                                        pV1, pAhi, pAlo);

    split_wT<<<gWT, 256>>>(Wo + W2, pWThi, pWTlo);
    mma_nn_bf16<<<gBig, 256, MMA_DSM>>>(pAhi, pAlo, pWThi, pWTlo, bo + 512, out, NBS);

    finalize_kernel<<<1, 1>>>(out, out_size);
}